// round 4
// baseline (speedup 1.0000x reference)
#include <cuda_runtime.h>

#define N_NODES 4096
#define D_EMB   256
#define H_HEADS 4
#define DH      64
#define E_EDGES 131072
#define MAXDEG  256
#define ALPHA   0.2f
#define BITW    (N_NODES / 32)   // 128 words per row

// ---- scratch (no allocations allowed; __device__ globals per harness rules) ----
__device__ unsigned g_bits[N_NODES * BITW];      // 2 MB dedup bitmask
__device__ int      g_deg [N_NODES];
__device__ int      g_nbr [N_NODES * MAXDEG];    // 4 MB CSR-ish neighbor slots
__device__ float    g_h   [N_NODES * D_EMB];     // 4 MB  h[i][head*64+k]
__device__ float    g_esrc[H_HEADS * N_NODES];
__device__ float    g_edst[H_HEADS * N_NODES];
__device__ float    g_hmean[D_EMB];              // fallback for deg==0 rows

// ---------------------------------------------------------------------------
// 1. clear scratch that must be zero every launch (graph replays!)
// ---------------------------------------------------------------------------
__global__ void k_clear() {
    int i = blockIdx.x * blockDim.x + threadIdx.x;
    int stride = gridDim.x * blockDim.x;
    for (int j = i; j < N_NODES * BITW; j += stride) g_bits[j] = 0u;
    for (int j = i; j < N_NODES; j += stride)        g_deg[j]  = 0;
    for (int j = i; j < D_EMB; j += stride)          g_hmean[j] = 0.f;
}

// ---------------------------------------------------------------------------
// 2. build deduplicated adjacency lists.
//    mask condition: new_vals>0 <=> edge_vals>0 (sigmoid strictly positive
//    for this weight distribution; see analysis). Dedup via bitmask atomicOr.
// ---------------------------------------------------------------------------
__global__ void k_build(const int* __restrict__ ei, const float* __restrict__ ev) {
    int e = blockIdx.x * blockDim.x + threadIdx.x;
    if (e >= E_EDGES) return;
    if (!(ev[e] > 0.f)) return;
    int r = ei[e];
    int c = ei[E_EDGES + e];
    unsigned bit = 1u << (c & 31);
    unsigned old = atomicOr(&g_bits[r * BITW + (c >> 5)], bit);
    if (!(old & bit)) {
        int p = atomicAdd(&g_deg[r], 1);
        if (p < MAXDEG) g_nbr[r * MAXDEG + p] = c;
    }
}

// ---------------------------------------------------------------------------
// 3. h = x @ Wf  where Wf[d][h*64+k] = W[h][d][k].  fp32 tiled GEMM.
//    4096x256 @ 256x256. BM=BN=64, BK=32, 256 threads, 4x4 microtile.
// ---------------------------------------------------------------------------
__global__ void k_gemm(const float* __restrict__ x, const float* __restrict__ W) {
    __shared__ float xs[32][65];   // [k][m], padded vs bank conflicts
    __shared__ float ws[32][65];   // [k][n]
    int tid = threadIdx.x;
    int tm = (tid >> 4) << 2;      // 0..60
    int tn = (tid & 15) << 2;      // 0..60
    int bm = blockIdx.x * 64;
    int bn = blockIdx.y * 64;
    float acc[4][4] = {};

    for (int k0 = 0; k0 < D_EMB; k0 += 32) {
        // load x tile: warp reads contiguous 128B rows, stores transposed
        #pragma unroll
        for (int l = 0; l < 8; l++) {
            int idx = tid + l * 256;          // 0..2047 = 64 rows x 32 k
            int r = idx >> 5, c = idx & 31;
            xs[c][r] = x[(bm + r) * D_EMB + k0 + c];
        }
        // load W tile: Wf[k0+c][bn+n] = W[(col>>6)*16384 + (k0+c)*64 + (col&63)]
        #pragma unroll
        for (int l = 0; l < 8; l++) {
            int idx = tid + l * 256;          // 32 k x 64 n
            int c = idx >> 6, n = idx & 63;
            int col = bn + n;
            ws[c][n] = W[(col >> 6) * (D_EMB * DH) + (k0 + c) * DH + (col & 63)];
        }
        __syncthreads();
        #pragma unroll
        for (int k = 0; k < 32; k++) {
            float a0 = xs[k][tm], a1 = xs[k][tm+1], a2 = xs[k][tm+2], a3 = xs[k][tm+3];
            float b0 = ws[k][tn], b1 = ws[k][tn+1], b2 = ws[k][tn+2], b3 = ws[k][tn+3];
            acc[0][0] += a0*b0; acc[0][1] += a0*b1; acc[0][2] += a0*b2; acc[0][3] += a0*b3;
            acc[1][0] += a1*b0; acc[1][1] += a1*b1; acc[1][2] += a1*b2; acc[1][3] += a1*b3;
            acc[2][0] += a2*b0; acc[2][1] += a2*b1; acc[2][2] += a2*b2; acc[2][3] += a2*b3;
            acc[3][0] += a3*b0; acc[3][1] += a3*b1; acc[3][2] += a3*b2; acc[3][3] += a3*b3;
        }
        __syncthreads();
    }
    #pragma unroll
    for (int u = 0; u < 4; u++)
        #pragma unroll
        for (int v = 0; v < 4; v++)
            g_h[(bm + tm + u) * D_EMB + bn + tn + v] = acc[u][v];
}

// ---------------------------------------------------------------------------
// 4. esrc[h][i] = h[i,h,:]·a_src[h], edst likewise. One warp per (i,h).
// ---------------------------------------------------------------------------
__global__ void k_coef(const float* __restrict__ a_src, const float* __restrict__ a_dst) {
    int w    = (blockIdx.x * blockDim.x + threadIdx.x) >> 5;
    int lane = threadIdx.x & 31;
    int nw   = (gridDim.x * blockDim.x) >> 5;
    for (int p = w; p < N_NODES * H_HEADS; p += nw) {
        int i = p >> 2, hh = p & 3;
        float v0 = g_h[i * D_EMB + hh * DH + lane];
        float v1 = g_h[i * D_EMB + hh * DH + 32 + lane];
        float s = v0 * a_src[hh * DH + lane] + v1 * a_src[hh * DH + 32 + lane];
        float d = v0 * a_dst[hh * DH + lane] + v1 * a_dst[hh * DH + 32 + lane];
        #pragma unroll
        for (int o = 16; o; o >>= 1) {
            s += __shfl_xor_sync(0xffffffffu, s, o);
            d += __shfl_xor_sync(0xffffffffu, d, o);
        }
        if (lane == 0) {
            g_esrc[hh * N_NODES + i] = s;
            g_edst[hh * N_NODES + i] = d;
        }
    }
}

// ---------------------------------------------------------------------------
// 5. column mean of h (reference softmax degenerates to uniform 1/N if a
//    node has zero unmasked neighbors; P~1e-14 but cheap insurance).
// ---------------------------------------------------------------------------
__global__ void k_hmean() {
    int c  = threadIdx.x;                 // 256 threads = 256 cols
    int r0 = blockIdx.x * 64;             // 64 blocks x 64 rows
    float s = 0.f;
    #pragma unroll 8
    for (int r = 0; r < 64; r++) s += g_h[(r0 + r) * D_EMB + c];
    atomicAdd(&g_hmean[c], s * (1.0f / N_NODES));
}

// ---------------------------------------------------------------------------
// 6. sparse GAT: one block (256 thr) per row i.
//    phase1: e[h][j] = leaky(esrc[h][i] + edst[h][nbr[j]])
//    phase2: per-head warp softmax (max, sum-exp) over deg entries
//    phase3: out[i][h*64+k] = sum_j w[h][j] * h[nbr[j]][h*64+k]
// ---------------------------------------------------------------------------
__global__ void k_gat(float* __restrict__ out) {
    __shared__ int   nbr_s[MAXDEG];
    __shared__ float e_s[H_HEADS][MAXDEG];
    __shared__ float m_s[H_HEADS], s_s[H_HEADS];

    int i = blockIdx.x;
    int t = threadIdx.x;
    int deg = min(g_deg[i], MAXDEG);

    if (t < deg) nbr_s[t] = g_nbr[i * MAXDEG + t];
    __syncthreads();

    if (t < deg) {
        int c = nbr_s[t];
        #pragma unroll
        for (int hh = 0; hh < H_HEADS; hh++) {
            float v = g_esrc[hh * N_NODES + i] + g_edst[hh * N_NODES + c];
            e_s[hh][t] = (v >= 0.f) ? v : ALPHA * v;
        }
    }
    __syncthreads();

    if (t < 128) {
        int hh = t >> 5, lane = t & 31;
        float m = -3.0e38f;
        for (int j = lane; j < deg; j += 32) m = fmaxf(m, e_s[hh][j]);
        #pragma unroll
        for (int o = 16; o; o >>= 1) m = fmaxf(m, __shfl_xor_sync(0xffffffffu, m, o));
        float s = 0.f;
        for (int j = lane; j < deg; j += 32) s += __expf(e_s[hh][j] - m);
        #pragma unroll
        for (int o = 16; o; o >>= 1) s += __shfl_xor_sync(0xffffffffu, s, o);
        if (lane == 0) {
            m_s[hh] = m;
            s_s[hh] = (s > 0.f) ? (1.0f / s) : 0.f;
        }
    }
    __syncthreads();

    if (t < deg) {
        #pragma unroll
        for (int hh = 0; hh < H_HEADS; hh++)
            e_s[hh][t] = __expf(e_s[hh][t] - m_s[hh]) * s_s[hh];
    }
    __syncthreads();

    int hh = t >> 6;
    const float* ep = e_s[hh];
    float acc = 0.f;
    int j = 0;
    for (; j + 4 <= deg; j += 4) {
        float w0 = ep[j], w1 = ep[j+1], w2 = ep[j+2], w3 = ep[j+3];
        float h0 = g_h[nbr_s[j]   * D_EMB + t];
        float h1 = g_h[nbr_s[j+1] * D_EMB + t];
        float h2 = g_h[nbr_s[j+2] * D_EMB + t];
        float h3 = g_h[nbr_s[j+3] * D_EMB + t];
        acc += w0 * h0 + w1 * h1 + w2 * h2 + w3 * h3;
    }
    for (; j < deg; j++) acc += ep[j] * g_h[nbr_s[j] * D_EMB + t];

    if (deg == 0) acc = g_hmean[t];
    out[i * D_EMB + t] = acc;
}

// ---------------------------------------------------------------------------
// launch: inputs per metadata order:
// 0 x[4096,256] 1 edge_vals[131072] 2 W1 3 b1 4 W2 5 b2 (2..5 unused — mask
// only depends on sign; see analysis) 6 W[4,256,64] 7 a_src[4,64]
// 8 a_dst[4,64] 9 edge_index[2,131072]
// ---------------------------------------------------------------------------
extern "C" void kernel_launch(void* const* d_in, const int* in_sizes, int n_in,
                              void* d_out, int out_size) {
    const float* x     = (const float*)d_in[0];
    const float* ev    = (const float*)d_in[1];
    const float* W     = (const float*)d_in[6];
    const float* a_src = (const float*)d_in[7];
    const float* a_dst = (const float*)d_in[8];
    const int*   ei    = (const int*)d_in[9];
    float* out = (float*)d_out;

    k_clear<<<512, 256>>>();
    k_build<<<E_EDGES / 256, 256>>>(ei, ev);
    k_gemm<<<dim3(N_NODES / 64, D_EMB / 64), 256>>>(x, W);
    k_coef<<<128, 256>>>(a_src, a_dst);
    k_hmean<<<64, 256>>>();
    k_gat<<<N_NODES, 256>>>(out);
}